// round 16
// baseline (speedup 1.0000x reference)
#include <cuda_runtime.h>
#include <cuda_bf16.h>

#define NT 256

// B=256, T=16, O=32, E=32, I=32, H=HL=64, TE=512, EI=64, P=496
// grid=128, 2 batches/CTA. Edge GEMM + agg/le1/lt2 on HMMA bf16 3-term split.
// hmma32 is __noinline__ to contain register pressure (R12-R14 all spilled at 255
// with it inlined at multiple sites; R11 edge-only was 160 regs).

struct Params {
    const float* z;
    const float *ee1_w,*ee1_b,*ee2_w,*ee2_b,*ee3_w,*ee3_b;
    const float *ne1_w,*ne1_b,*ne2_w,*ne2_b,*ne3_w,*ne3_b,*ne4_w,*ne4_b;
    const float *le1_w,*le1_b,*le2_w,*le2_b,*le3_w,*le3_b;
    const float *lt1_w,*lt1_b,*lt2_w,*lt2_b,*lt3_w,*lt3_b,*lt4_w,*lt4_b,*lt5_w,*lt5_b;
    float* out;
    int t_future;
};

// pre-split weights Bt[n][k], bf16 hi/lo:
// 0=ee2, 1=le2, 2=le1a, 3=le1b, 4=lt2, 5=ee3, 6=le3
__device__ unsigned short g_Bh[7][4096];
__device__ unsigned short g_Bl[7][4096];

__global__ void prep_kernel(const float* ee2, const float* le2,
                            const float* le1, const float* lt2,
                            const float* ee3, const float* le3)
{
    const float* srcs[7] = { ee2, le2, le1, le1 + 4096, lt2, ee3, le3 };
    int b = blockIdx.x;
    const float* W = srcs[b];
    for (int idx = threadIdx.x; idx < 4096; idx += blockDim.x) {
        int n = idx >> 6, k = idx & 63;
        float w = W[k * 64 + n];
        unsigned u = __float_as_uint(w);
        unsigned short hb = (unsigned short)(u >> 16);
        float hf = __uint_as_float(u & 0xFFFF0000u);
        __nv_bfloat16 lb = __float2bfloat16(w - hf);
        g_Bh[b][n * 64 + k] = hb;
        g_Bl[b][n * 64 + k] = *(unsigned short*)&lb;
    }
}

// ---- smem layout (byte offsets) ----
#define SM_H2    0        // 512*68*4 = 139264 (scratch aliases inside)
#define SM_ACT   139264   // ya0,ya1,yb0,yb1 (32*66) + zc0,zc1 (2048)
#define SM_JL    189440   // 1024 u16
#define SM_II    191488
#define SM_JJ    192000
#define SM_B2    192512   // 64 floats
#define SMEM_BYTES 192768

#define YAP 66
#define H2P 68

__device__ __forceinline__ void fma4(float* acc, float a, const float4& w) {
    acc[0] = fmaf(a, w.x, acc[0]);
    acc[1] = fmaf(a, w.y, acc[1]);
    acc[2] = fmaf(a, w.z, acc[2]);
    acc[3] = fmaf(a, w.w, acc[3]);
}

// ---- HMMA primitives ----
__device__ __forceinline__ void mma16816(float* d, const unsigned* a, unsigned b0, unsigned b1) {
    asm volatile(
        "mma.sync.aligned.m16n8k16.row.col.f32.bf16.bf16.f32 "
        "{%0,%1,%2,%3}, {%4,%5,%6,%7}, {%8,%9}, {%0,%1,%2,%3};"
        : "+f"(d[0]), "+f"(d[1]), "+f"(d[2]), "+f"(d[3])
        : "r"(a[0]), "r"(a[1]), "r"(a[2]), "r"(a[3]), "r"(b0), "r"(b1));
}
__device__ __forceinline__ void split2(const float* p, int c, unsigned& hi, unsigned& lo) {
    float2 v = *(const float2*)(p + c);
    unsigned u0 = __float_as_uint(v.x), u1 = __float_as_uint(v.y);
    asm("prmt.b32 %0, %1, %2, 0x7632;" : "=r"(hi) : "r"(u0), "r"(u1));
    float h0 = __uint_as_float(u0 & 0xFFFF0000u);
    float h1 = __uint_as_float(u1 & 0xFFFF0000u);
    asm("cvt.rn.bf16x2.f32 %0, %1, %2;" : "=r"(lo) : "f"(v.y - h1), "f"(v.x - h0));
}
__device__ __forceinline__ void build_pair(const float* pa, const float* pb, int c,
                                           unsigned& hi, unsigned& lo) {
    float2 va = *(const float2*)(pa + c);
    float2 vb = *(const float2*)(pb + c);
    float v0 = fmaxf(va.x + vb.x, 0.f);
    float v1 = fmaxf(va.y + vb.y, 0.f);
    unsigned u0 = __float_as_uint(v0), u1 = __float_as_uint(v1);
    asm("prmt.b32 %0, %1, %2, 0x7632;" : "=r"(hi) : "r"(u0), "r"(u1));
    float h0 = __uint_as_float(u0 & 0xFFFF0000u);
    float h1 = __uint_as_float(u1 & 0xFFFF0000u);
    asm("cvt.rn.bf16x2.f32 %0, %1, %2;" : "=r"(lo) : "f"(v1 - h1), "f"(v0 - h0));
}

// ---- lean fused 2-batch 32x64x64 HMMA layer (write-only output, no ACC) ----
// __noinline__: isolates register allocation from the main kernel body.
// 8 warps: m=wid&3 (16-row tile, m<2 batch0 else batch1), nh=wid>>2 (32-col half).
// BIASMODE: 0 none, 1 bias[col], 2 (31-2row)*bias[col].
template<bool RELU, int BIASMODE, int OP>
__device__ __noinline__ void hmma32(const float* __restrict__ X0,
                                    const float* __restrict__ X1,
                                    const unsigned short* __restrict__ Bh,
                                    const unsigned short* __restrict__ Bl,
                                    const float* __restrict__ bias,
                                    float* O0, float* O1, int tid)
{
    const int wid = tid >> 5, lane = tid & 31;
    const int g = lane >> 2, t = lane & 3;
    const int m = wid & 3, nh = wid >> 2;
    const int rl = (m & 1) * 16 + g;
    const float* X = (m < 2) ? X0 : X1;
    float* O = (m < 2) ? O0 : O1;
    const float* p0 = X + rl * 64;
    const float* p1 = X + (rl + 8) * 64;
    unsigned Ahi[4][4], Alo[4][4];
#pragma unroll
    for (int ks = 0; ks < 4; ks++) {
        int c = ks * 16 + 2 * t;
        split2(p0, c,     Ahi[ks][0], Alo[ks][0]);
        split2(p1, c,     Ahi[ks][1], Alo[ks][1]);
        split2(p0, c + 8, Ahi[ks][2], Alo[ks][2]);
        split2(p1, c + 8, Ahi[ks][3], Alo[ks][3]);
    }
#pragma unroll
    for (int ns = 0; ns < 4; ns++) {
        const int n = nh * 32 + ns * 8 + g;
        const unsigned short* bh = Bh + n * 64;
        const unsigned short* bl = Bl + n * 64;
        float da[4] = {0,0,0,0}, db[4] = {0,0,0,0}, dc[4] = {0,0,0,0};
#pragma unroll
        for (int ks = 0; ks < 4; ks++) {
            int kb = ks * 16 + 2 * t;
            unsigned bh0 = *(const unsigned*)(bh + kb);
            unsigned bh1 = *(const unsigned*)(bh + kb + 8);
            unsigned bl0 = *(const unsigned*)(bl + kb);
            unsigned bl1 = *(const unsigned*)(bl + kb + 8);
            mma16816(da, Ahi[ks], bh0, bh1);
            mma16816(db, Ahi[ks], bl0, bl1);
            mma16816(dc, Alo[ks], bh0, bh1);
        }
        const int col = nh * 32 + ns * 8 + 2 * t;
        float s0 = da[0] + db[0] + dc[0];
        float s1 = da[1] + db[1] + dc[1];
        float s2 = da[2] + db[2] + dc[2];
        float s3 = da[3] + db[3] + dc[3];
        if (BIASMODE == 1) {
            float b0v = bias[col], b1v = bias[col + 1];
            s0 += b0v; s1 += b1v; s2 += b0v; s3 += b1v;
        } else if (BIASMODE == 2) {
            float b0v = bias[col], b1v = bias[col + 1];
            float sl = (float)(31 - 2 * rl), sh = (float)(31 - 2 * (rl + 8));
            s0 += sl * b0v; s1 += sl * b1v; s2 += sh * b0v; s3 += sh * b1v;
        }
        if (RELU) {
            s0 = fmaxf(s0, 0.f); s1 = fmaxf(s1, 0.f);
            s2 = fmaxf(s2, 0.f); s3 = fmaxf(s3, 0.f);
        }
        *(float2*)(O + rl * OP + col) = make_float2(s0, s1);
        *(float2*)(O + (rl + 8) * OP + col) = make_float2(s2, s3);
    }
}

// ---- scalar blocks (R11 heritage) ----
template<int IN, bool ACC, bool RELU, int OP>
__device__ __forceinline__ void layer2(const float* __restrict__ in0,
                                       const float* __restrict__ in1,
                                       const float* __restrict__ W,
                                       const float* __restrict__ bias,
                                       float* __restrict__ out0,
                                       float* __restrict__ out1, int tid)
{
    const int c0 = (tid & 15) * 4;
    const int r0 = (tid >> 4) * 2;
    float acc[2][2][4];
    if (ACC) {
#pragma unroll
        for (int i = 0; i < 2; i++)
#pragma unroll
            for (int j = 0; j < 4; j++) {
                acc[0][i][j] = out0[(r0 + i) * OP + c0 + j];
                acc[1][i][j] = out1[(r0 + i) * OP + c0 + j];
            }
    } else {
#pragma unroll
        for (int j = 0; j < 4; j++) {
            float bv = bias ? bias[c0 + j] : 0.f;
            acc[0][0][j] = bv; acc[0][1][j] = bv;
            acc[1][0][j] = bv; acc[1][1][j] = bv;
        }
    }
    const float* i00 = in0 + r0 * IN;
    const float* i01 = i00 + IN;
    const float* i10 = in1 + r0 * IN;
    const float* i11 = i10 + IN;
#pragma unroll 4
    for (int k = 0; k < IN; k += 4) {
        float4 w0 = *(const float4*)(W + (k + 0) * 64 + c0);
        float4 w1 = *(const float4*)(W + (k + 1) * 64 + c0);
        float4 w2 = *(const float4*)(W + (k + 2) * 64 + c0);
        float4 w3 = *(const float4*)(W + (k + 3) * 64 + c0);
        float4 a;
        a = *(const float4*)(i00 + k);
        fma4(acc[0][0], a.x, w0); fma4(acc[0][0], a.y, w1); fma4(acc[0][0], a.z, w2); fma4(acc[0][0], a.w, w3);
        a = *(const float4*)(i01 + k);
        fma4(acc[0][1], a.x, w0); fma4(acc[0][1], a.y, w1); fma4(acc[0][1], a.z, w2); fma4(acc[0][1], a.w, w3);
        a = *(const float4*)(i10 + k);
        fma4(acc[1][0], a.x, w0); fma4(acc[1][0], a.y, w1); fma4(acc[1][0], a.z, w2); fma4(acc[1][0], a.w, w3);
        a = *(const float4*)(i11 + k);
        fma4(acc[1][1], a.x, w0); fma4(acc[1][1], a.y, w1); fma4(acc[1][1], a.z, w2); fma4(acc[1][1], a.w, w3);
    }
#pragma unroll
    for (int i = 0; i < 2; i++)
#pragma unroll
        for (int j = 0; j < 4; j++) {
            float v0 = acc[0][i][j], v1 = acc[1][i][j];
            if (RELU) { v0 = fmaxf(v0, 0.f); v1 = fmaxf(v1, 0.f); }
            out0[(r0 + i) * OP + c0 + j] = v0;
            out1[(r0 + i) * OP + c0 + j] = v1;
        }
}

__device__ __forceinline__ void layer_small_2(const float* __restrict__ in0,
                                              const float* __restrict__ in1, int IN,
                                              const float* __restrict__ W,
                                              const float* __restrict__ bias,
                                              float* __restrict__ out0,
                                              float* __restrict__ out1, int OUT,
                                              bool relu, int tid)
{
    for (int idx = tid; idx < 32 * OUT; idx += NT) {
        int r = idx / OUT, c = idx % OUT;
        float a0 = bias[c], a1 = a0;
        const float* i0 = in0 + r * IN;
        const float* i1 = in1 + r * IN;
#pragma unroll 4
        for (int k = 0; k < IN; k++) {
            float w = W[k * OUT + c];
            a0 = fmaf(i0[k], w, a0);
            a1 = fmaf(i1[k], w, a1);
        }
        out0[idx] = relu ? fmaxf(a0, 0.f) : a0;
        out1[idx] = relu ? fmaxf(a1, 0.f) : a1;
    }
}

__device__ __forceinline__ void acc_chunk2(const float* __restrict__ s0,
                                           const float* __restrict__ s1,
                                           const float* __restrict__ Wg,
                                           float acc[2][2][4], int r0, int c0)
{
    const float* a00 = s0 + r0 * 64;
    const float* a01 = a00 + 64;
    const float* a10 = s1 + r0 * 64;
    const float* a11 = a10 + 64;
#pragma unroll 4
    for (int k = 0; k < 64; k += 4) {
        float4 w0 = *(const float4*)(Wg + (k + 0) * 64 + c0);
        float4 w1 = *(const float4*)(Wg + (k + 1) * 64 + c0);
        float4 w2 = *(const float4*)(Wg + (k + 2) * 64 + c0);
        float4 w3 = *(const float4*)(Wg + (k + 3) * 64 + c0);
        float4 a;
        a = *(const float4*)(a00 + k);
        fma4(acc[0][0], a.x, w0); fma4(acc[0][0], a.y, w1); fma4(acc[0][0], a.z, w2); fma4(acc[0][0], a.w, w3);
        a = *(const float4*)(a01 + k);
        fma4(acc[0][1], a.x, w0); fma4(acc[0][1], a.y, w1); fma4(acc[0][1], a.z, w2); fma4(acc[0][1], a.w, w3);
        a = *(const float4*)(a10 + k);
        fma4(acc[1][0], a.x, w0); fma4(acc[1][0], a.y, w1); fma4(acc[1][0], a.z, w2); fma4(acc[1][0], a.w, w3);
        a = *(const float4*)(a11 + k);
        fma4(acc[1][1], a.x, w0); fma4(acc[1][1], a.y, w1); fma4(acc[1][1], a.z, w2); fma4(acc[1][1], a.w, w3);
    }
}

// per-warp HMMA edge GEMM for one batch: h2[512][H2P] = relu(relu(ya[ii]+yb[jj]) @ W2 + b2)
__device__ __forceinline__ void edge_gemm_mma(const float* __restrict__ ya,
                                              const float* __restrict__ yb,
                                              const unsigned short* __restrict__ Bth,
                                              const unsigned short* __restrict__ Btl,
                                              const float* __restrict__ b2s,
                                              float* __restrict__ h2f,
                                              const unsigned char* __restrict__ ii,
                                              const unsigned char* __restrict__ jj,
                                              int tid)
{
    const int wid = tid >> 5, lane = tid & 31;
    const int g = lane >> 2, t = lane & 3;
#pragma unroll 1
    for (int mt = 0; mt < 4; mt++) {
        const int tb = (wid * 4 + mt) * 16;
        const int r0 = tb + g, r1 = r0 + 8;
        const float* pa0 = ya + ii[r0] * YAP;
        const float* pb0 = yb + jj[r0] * YAP;
        const float* pa1 = ya + ii[r1] * YAP;
        const float* pb1 = yb + jj[r1] * YAP;
        unsigned Ahi[4][4], Alo[4][4];
#pragma unroll
        for (int ks = 0; ks < 4; ks++) {
            int c = ks * 16 + 2 * t;
            build_pair(pa0, pb0, c,     Ahi[ks][0], Alo[ks][0]);
            build_pair(pa1, pb1, c,     Ahi[ks][1], Alo[ks][1]);
            build_pair(pa0, pb0, c + 8, Ahi[ks][2], Alo[ks][2]);
            build_pair(pa1, pb1, c + 8, Ahi[ks][3], Alo[ks][3]);
        }
#pragma unroll
        for (int ns = 0; ns < 8; ns++) {
            const int n = ns * 8 + g;
            const unsigned short* bh = Bth + n * 64;
            const unsigned short* bl = Btl + n * 64;
            float da[4] = {0,0,0,0}, db[4] = {0,0,0,0}, dc[4] = {0,0,0,0};
#pragma unroll
            for (int ks = 0; ks < 4; ks++) {
                int kb = ks * 16 + 2 * t;
                unsigned bh0 = *(const unsigned*)(bh + kb);
                unsigned bh1 = *(const unsigned*)(bh + kb + 8);
                unsigned bl0 = *(const unsigned*)(bl + kb);
                unsigned bl1 = *(const unsigned*)(bl + kb + 8);
                mma16816(da, Ahi[ks], bh0, bh1);
                mma16816(db, Ahi[ks], bl0, bl1);
                mma16816(dc, Alo[ks], bh0, bh1);
            }
            int col = ns * 8 + 2 * t;
            float b0v = b2s[col], b1v = b2s[col + 1];
            float2 o0, o1;
            o0.x = fmaxf(da[0] + db[0] + dc[0] + b0v, 0.f);
            o0.y = fmaxf(da[1] + db[1] + dc[1] + b1v, 0.f);
            o1.x = fmaxf(da[2] + db[2] + dc[2] + b0v, 0.f);
            o1.y = fmaxf(da[3] + db[3] + dc[3] + b1v, 0.f);
            *(float2*)(h2f + r0 * H2P + col) = o0;
            *(float2*)(h2f + r1 * H2P + col) = o1;
        }
    }
}

// full edge block: 2 batches -> agg0/agg1; agg GEMM on HMMA (biasmode 2)
__device__ void edge_full(const float* ya0, const float* ya1,
                          const float* yb0, const float* yb1,
                          const unsigned short* B2h, const unsigned short* B2l,
                          const float* b2s,
                          const unsigned short* B3h, const unsigned short* B3l,
                          const float* __restrict__ b3g,
                          float* h2f, float* Gs0, float* Gs1,
                          float* agg0, float* agg1,
                          const unsigned char* ii, const unsigned char* jj,
                          const unsigned short* jl, int tid)
{
    const int n = tid >> 3, c0s = (tid & 7) * 8;
    const int rs = n * 31 - ((n * (n - 1)) >> 1);
    const int iiend = rs + 31 - n;
    float g2[2][8];
#pragma unroll
    for (int j = 0; j < 8; j++) { g2[0][j] = 0.f; g2[1][j] = 0.f; }

#pragma unroll 1
    for (int b = 0; b < 2; b++) {
        edge_gemm_mma(b ? ya1 : ya0, b ? yb1 : yb0, B2h, B2l, b2s, h2f, ii, jj, tid);
        __syncthreads();
        float* g = g2[b];
        for (int p = rs; p < iiend; p++) {
            const float* r = h2f + p * H2P + c0s;
            float4 v0 = *(const float4*)r, v1 = *(const float4*)(r + 4);
            g[0] += v0.x; g[1] += v0.y; g[2] += v0.z; g[3] += v0.w;
            g[4] += v1.x; g[5] += v1.y; g[6] += v1.z; g[7] += v1.w;
        }
        for (int k = 0; k < n; k++) {
            int p = jl[(n << 5) + k];
            const float* r = h2f + p * H2P + c0s;
            float4 v0 = *(const float4*)r, v1 = *(const float4*)(r + 4);
            g[0] -= v0.x; g[1] -= v0.y; g[2] -= v0.z; g[3] -= v0.w;
            g[4] -= v1.x; g[5] -= v1.y; g[6] -= v1.z; g[7] -= v1.w;
        }
        __syncthreads();
    }
#pragma unroll
    for (int j = 0; j < 8; j++) {
        Gs0[n * 64 + c0s + j] = g2[0][j];
        Gs1[n * 64 + c0s + j] = g2[1][j];
    }
    __syncthreads();
    hmma32<false, 2, 64>(Gs0, Gs1, B3h, B3l, b3g, agg0, agg1, tid);
    __syncthreads();
}

__global__ void __launch_bounds__(NT, 1)
RelationalLatentDynamics_82849919140105_kernel(Params P)
{
    extern __shared__ char smb[];
    float* h2f = (float*)(smb + SM_H2);
    float* sc0  = h2f;            // scratch aliases in h2f
    float* sc1  = h2f + 4096;
    float* t0   = h2f + 8192;
    float* t1   = h2f + 10240;
    float* Gs0  = h2f + 12288;
    float* Gs1  = h2f + 14336;
    float* agg0 = h2f + 16384;
    float* agg1 = h2f + 18432;
    float* act = (float*)(smb + SM_ACT);
    float* ya0 = act;              float* ya1 = act + 2112;
    float* yb0 = act + 4224;       float* yb1 = act + 6336;
    float* zc0 = act + 8448;       float* zc1 = act + 10496;
    unsigned short* s_jl = (unsigned short*)(smb + SM_JL);
    unsigned char*  s_ii = (unsigned char*)(smb + SM_II);
    unsigned char*  s_jj = (unsigned char*)(smb + SM_JJ);
    float* b2s = (float*)(smb + SM_B2);

    const int tid = threadIdx.x;
    const int c0 = (tid & 15) * 4;
    const int r0 = (tid >> 4) * 2;

    for (int p = tid; p < 512; p += NT) {
        if (p < 496) {
            int pp = p, i = 0;
            while (pp >= 31 - i) { pp -= 31 - i; i++; }
            s_ii[p] = (unsigned char)i;
            s_jj[p] = (unsigned char)(i + 1 + pp);
        } else { s_ii[p] = 0; s_jj[p] = 1; }
    }
    for (int idx = tid; idx < 1024; idx += NT) {
        int nn = idx >> 5, k = idx & 31;
        s_jl[idx] = (k < nn)
            ? (unsigned short)(k * 31 - ((k * (k - 1)) >> 1) + (nn - k - 1))
            : (unsigned short)0xFFFF;
    }
    if (tid < 64) b2s[tid] = P.ee2_b[tid];
    __syncthreads();

    const float* zb0 = P.z + (size_t)(2 * blockIdx.x) * (16 * 32 * 32);
    const float* zb1 = zb0 + 16 * 32 * 32;

    // ---- Phase A: ya/yb = src @ ee1_w (streamed; ee1_b folded into ya; pitch YAP) ----
    {
        float accA[2][2][4], accB[2][2][4];
#pragma unroll
        for (int j = 0; j < 4; j++) {
            float bv = P.ee1_b[c0 + j];
            accA[0][0][j] = bv; accA[0][1][j] = bv; accA[1][0][j] = bv; accA[1][1][j] = bv;
            accB[0][0][j] = 0.f; accB[0][1][j] = 0.f; accB[1][0][j] = 0.f; accB[1][1][j] = 0.f;
        }
#pragma unroll 1
        for (int ch = 0; ch < 8; ch++) {
            for (int idx = tid; idx < 2048; idx += NT) {
                int o = idx >> 6, fl = idx & 63;
                int t = 2 * ch + (fl >> 5), e = fl & 31;
                int off = (t * 32 + o) * 32 + e;
                float v0 = zb0[off], v1 = zb1[off];
                if (t > 0) { v0 -= zb0[off - 1024]; v1 -= zb1[off - 1024]; }
                sc0[o * 64 + fl] = v0;
                sc1[o * 64 + fl] = v1;
            }
            __syncthreads();
            acc_chunk2(sc0, sc1, P.ee1_w + ch * 4096, accA, r0, c0);
            acc_chunk2(sc0, sc1, P.ee1_w + 512 * 64 + ch * 4096, accB, r0, c0);
            __syncthreads();
        }
#pragma unroll
        for (int i = 0; i < 2; i++)
#pragma unroll
            for (int j = 0; j < 4; j++) {
                ya0[(r0 + i) * YAP + c0 + j] = accA[0][i][j];
                ya1[(r0 + i) * YAP + c0 + j] = accA[1][i][j];
                yb0[(r0 + i) * YAP + c0 + j] = accB[0][i][j];
                yb1[(r0 + i) * YAP + c0 + j] = accB[1][i][j];
            }
    }
    __syncthreads();

    // ---- ee edge block (HMMA, weights idx 0/5) ----
    edge_full(ya0, ya1, yb0, yb1, g_Bh[0], g_Bl[0], b2s, g_Bh[5], g_Bl[5], P.ee3_b,
              h2f, Gs0, Gs1, agg0, agg1, s_ii, s_jj, s_jl, tid);

    // ---- ne MLP (scalar; ya reused pitch-64) ----
    layer2<64, false, false, 64>(agg0, agg1, P.ne1_w + 512 * 64, P.ne1_b, ya0, ya1, tid);
    {
        float acc[2][2][4];
#pragma unroll
        for (int i = 0; i < 2; i++)
#pragma unroll
            for (int j = 0; j < 4; j++) {
                acc[0][i][j] = ya0[(r0 + i) * 64 + c0 + j];
                acc[1][i][j] = ya1[(r0 + i) * 64 + c0 + j];
            }
#pragma unroll 1
        for (int ch = 0; ch < 8; ch++) {
            for (int idx = tid; idx < 2048; idx += NT) {
                int o = idx >> 6, fl = idx & 63;
                int t = 2 * ch + (fl >> 5), e = fl & 31;
                int off = (t * 32 + o) * 32 + e;
                float v0 = zb0[off], v1 = zb1[off];
                if (t > 0) { v0 -= zb0[off - 1024]; v1 -= zb1[off - 1024]; }
                sc0[o * 64 + fl] = v0;
                sc1[o * 64 + fl] = v1;
            }
            __syncthreads();
            acc_chunk2(sc0, sc1, P.ne1_w + ch * 4096, acc, r0, c0);
            __syncthreads();
        }
#pragma unroll
        for (int i = 0; i < 2; i++)
#pragma unroll
            for (int j = 0; j < 4; j++) {
                ya0[(r0 + i) * 64 + c0 + j] = fmaxf(acc[0][i][j], 0.f);
                ya1[(r0 + i) * 64 + c0 + j] = fmaxf(acc[1][i][j], 0.f);
            }
    }
    __syncthreads();
    layer2<64, false, true, 64>(ya0, ya1, P.ne2_w, P.ne2_b, sc0, sc1, tid);
    __syncthreads();
    layer_small_2(sc0, sc1, 64, P.ne3_w, P.ne3_b, t0, t1, 32, true, tid);
    __syncthreads();
    layer_small_2(t0, t1, 32, P.ne4_w, P.ne4_b, sc0, sc1, 32, false, tid);  // z_impl
    __syncthreads();

    // zc = concat(z[b,-1], z_impl); restage le2 bias
    const float* zl0 = zb0 + 15 * 32 * 32;
    const float* zl1 = zb1 + 15 * 32 * 32;
    for (int idx = tid; idx < 2048; idx += NT) {
        int o = idx >> 6, c = idx & 63;
        zc0[idx] = (c < 32) ? zl0[o * 32 + c] : sc0[o * 32 + (c - 32)];
        zc1[idx] = (c < 32) ? zl1[o * 32 + c] : sc1[o * 32 + (c - 32)];
    }
    if (tid < 64) b2s[tid] = P.le2_b[tid];
    __syncthreads();

    // ---- rollout ----
    const int ostride = P.t_future * 1024;
    float* out0 = P.out + (size_t)(2 * blockIdx.x) * ostride;
    float* out1 = out0 + ostride;
#pragma unroll 1
    for (int t = 0; t < P.t_future; t++) {
        // le1 (HMMA, write-only): ya = zc@le1a + b1; yb = zc@le1b
        hmma32<false, 1, YAP>(zc0, zc1, g_Bh[2], g_Bl[2], P.le1_b, ya0, ya1, tid);
        hmma32<false, 0, YAP>(zc0, zc1, g_Bh[3], g_Bl[3], nullptr, yb0, yb1, tid);
        __syncthreads();
        edge_full(ya0, ya1, yb0, yb1, g_Bh[1], g_Bl[1], b2s, g_Bh[6], g_Bl[6], P.le3_b,
                  h2f, Gs0, Gs1, agg0, agg1, s_ii, s_jj, s_jl, tid);

        // lt1 (scalar, K=128: zc then agg with ACC)
        layer2<64, false, false, 64>(zc0, zc1, P.lt1_w,            P.lt1_b, sc0, sc1, tid);
        layer2<64, true,  true,  64>(agg0, agg1, P.lt1_w + 64 * 64, nullptr, sc0, sc1, tid);
        __syncthreads();
        // lt2 (HMMA)
        hmma32<true, 1, 64>(sc0, sc1, g_Bh[4], g_Bl[4], P.lt2_b, t0, t1, tid);
        __syncthreads();
        layer_small_2(t0, t1, 64, P.lt3_w, P.lt3_b, sc0, sc1, 32, true, tid);
        __syncthreads();
        layer_small_2(sc0, sc1, 32, P.lt4_w, P.lt4_b, t0, t1, 16, true, tid);
        __syncthreads();
        layer2<16, false, false, 64>(t0, t1, P.lt5_w, P.lt5_b, sc0, sc1, tid);  // delta
        __syncthreads();

        for (int idx = tid; idx < 2048; idx += NT) {
            float zn0 = zc0[idx] + sc0[idx];
            float zn1 = zc1[idx] + sc1[idx];
            zc0[idx] = zn0; zc1[idx] = zn1;
            int o = idx >> 6, c = idx & 63;
            if (c < 32) {
                out0[t * 1024 + o * 32 + c] = zn0;
                out1[t * 1024 + o * 32 + c] = zn1;
            }
        }
        __syncthreads();
    }
}

extern "C" void kernel_launch(void* const* d_in, const int* in_sizes, int n_in,
                              void* d_out, int out_size)
{
    Params P;
    int i = 0;
    P.z     = (const float*)d_in[i++];
    P.ee1_w = (const float*)d_in[i++]; P.ee1_b = (const float*)d_in[i++];
    P.ee2_w = (const float*)d_in[i++]; P.ee2_b = (const float*)d_in[i++];
    P.ee3_w = (const float*)d_in[i++]; P.ee3_b = (const float*)d_in[i++];
    P.ne1_w = (const float*)d_in[i++]; P.ne1_b = (const float*)d_in[i++];
    P.ne2_w = (const float*)d_in[i++]; P.ne2_b = (const float*)d_in[i++];
    P.ne3_w = (const float*)d_in[i++]; P.ne3_b = (const float*)d_in[i++];
    P.ne4_w = (const float*)d_in[i++]; P.ne4_b = (const float*)d_in[i++];
    P.le1_w = (const float*)d_in[i++]; P.le1_b = (const float*)d_in[i++];
    P.le2_w = (const float*)d_in[i++]; P.le2_b = (const float*)d_in[i++];
    P.le3_w = (const float*)d_in[i++]; P.le3_b = (const float*)d_in[i++];
    P.lt1_w = (const float*)d_in[i++]; P.lt1_b = (const float*)d_in[i++];
    P.lt2_w = (const float*)d_in[i++]; P.lt2_b = (const float*)d_in[i++];
    P.lt3_w = (const float*)d_in[i++]; P.lt3_b = (const float*)d_in[i++];
    P.lt4_w = (const float*)d_in[i++]; P.lt4_b = (const float*)d_in[i++];
    P.lt5_w = (const float*)d_in[i++]; P.lt5_b = (const float*)d_in[i++];
    P.out = (float*)d_out;
    P.t_future = out_size / (256 * 32 * 32);

    prep_kernel<<<7, 256>>>(P.ee2_w, P.le2_w, P.le1_w, P.lt2_w, P.ee3_w, P.le3_w);

    cudaFuncSetAttribute(RelationalLatentDynamics_82849919140105_kernel,
                         cudaFuncAttributeMaxDynamicSharedMemorySize, SMEM_BYTES);
    RelationalLatentDynamics_82849919140105_kernel<<<128, NT, SMEM_BYTES>>>(P);
}

// round 17
// speedup vs baseline: 1.0672x; 1.0672x over previous
#include <cuda_runtime.h>
#include <cuda_bf16.h>

#define NT 256

// B=256, T=16, O=32, E=32, I=32, H=HL=64, TE=512, EI=64, P=496
// grid=128, 2 batches/CTA. Edge L2 GEMM on HMMA m16n8k16 bf16 (3-term split).
// R11 champion + prep kernel (pre-split edge weights; no in-kernel staging).

struct Params {
    const float* z;
    const float *ee1_w,*ee1_b,*ee2_w,*ee2_b,*ee3_w,*ee3_b;
    const float *ne1_w,*ne1_b,*ne2_w,*ne2_b,*ne3_w,*ne3_b,*ne4_w,*ne4_b;
    const float *le1_w,*le1_b,*le2_w,*le2_b,*le3_w,*le3_b;
    const float *lt1_w,*lt1_b,*lt2_w,*lt2_b,*lt3_w,*lt3_b,*lt4_w,*lt4_b,*lt5_w,*lt5_b;
    float* out;
    int t_future;
};

// pre-split edge weights Bt[n][k], bf16 hi/lo: 0=ee2, 1=le2
__device__ unsigned short g_Bh[2][4096];
__device__ unsigned short g_Bl[2][4096];

__global__ void prep_kernel(const float* ee2, const float* le2)
{
    const float* W = blockIdx.x ? le2 : ee2;
    int b = blockIdx.x;
    for (int idx = threadIdx.x; idx < 4096; idx += blockDim.x) {
        int n = idx >> 6, k = idx & 63;
        float w = W[k * 64 + n];
        unsigned u = __float_as_uint(w);
        unsigned short hb = (unsigned short)(u >> 16);
        float hf = __uint_as_float(u & 0xFFFF0000u);
        __nv_bfloat16 lb = __float2bfloat16(w - hf);
        g_Bh[b][n * 64 + k] = hb;
        g_Bl[b][n * 64 + k] = *(unsigned short*)&lb;
    }
}

// ---- smem layout (byte offsets) ----
#define SM_H2    0        // 512*68*4 = 139264 (scratch aliases inside)
#define SM_ACT   139264   // ya0,ya1,yb0,yb1 (32*66 fl) + zc0,zc1 (2048 fl)
#define SM_JL    189440   // 1024 u16
#define SM_II    191488
#define SM_JJ    192000
#define SM_B2    192512   // 64 floats
#define SMEM_BYTES 192768

#define YAP 66   // ya/yb pitch
#define H2P 68   // h2 pitch

__device__ __forceinline__ void fma4(float* acc, float a, const float4& w) {
    acc[0] = fmaf(a, w.x, acc[0]);
    acc[1] = fmaf(a, w.y, acc[1]);
    acc[2] = fmaf(a, w.z, acc[2]);
    acc[3] = fmaf(a, w.w, acc[3]);
}

// ---- HMMA primitives ----
__device__ __forceinline__ void mma16816(float* d, const unsigned* a, unsigned b0, unsigned b1) {
    asm volatile(
        "mma.sync.aligned.m16n8k16.row.col.f32.bf16.bf16.f32 "
        "{%0,%1,%2,%3}, {%4,%5,%6,%7}, {%8,%9}, {%0,%1,%2,%3};"
        : "+f"(d[0]), "+f"(d[1]), "+f"(d[2]), "+f"(d[3])
        : "r"(a[0]), "r"(a[1]), "r"(a[2]), "r"(a[3]), "r"(b0), "r"(b1));
}
// relu(ya+yb) for 2 consecutive cols -> packed bf16 hi (trunc) + lo (round)
__device__ __forceinline__ void build_pair(const float* pa, const float* pb, int c,
                                           unsigned& hi, unsigned& lo) {
    float2 va = *(const float2*)(pa + c);
    float2 vb = *(const float2*)(pb + c);
    float v0 = fmaxf(va.x + vb.x, 0.f);
    float v1 = fmaxf(va.y + vb.y, 0.f);
    unsigned u0 = __float_as_uint(v0), u1 = __float_as_uint(v1);
    asm("prmt.b32 %0, %1, %2, 0x7632;" : "=r"(hi) : "r"(u0), "r"(u1));
    float h0 = __uint_as_float(u0 & 0xFFFF0000u);
    float h1 = __uint_as_float(u1 & 0xFFFF0000u);
    asm("cvt.rn.bf16x2.f32 %0, %1, %2;" : "=r"(lo) : "f"(v1 - h1), "f"(v0 - h0));
}

// ---- scalar building blocks (R6/R11 heritage) ----
template<int IN, bool ACC, bool RELU, int OP>
__device__ __forceinline__ void layer2(const float* __restrict__ in0,
                                       const float* __restrict__ in1,
                                       const float* __restrict__ W,
                                       const float* __restrict__ bias,
                                       float* __restrict__ out0,
                                       float* __restrict__ out1, int tid)
{
    const int c0 = (tid & 15) * 4;
    const int r0 = (tid >> 4) * 2;
    float acc[2][2][4];
    if (ACC) {
#pragma unroll
        for (int i = 0; i < 2; i++)
#pragma unroll
            for (int j = 0; j < 4; j++) {
                acc[0][i][j] = out0[(r0 + i) * OP + c0 + j];
                acc[1][i][j] = out1[(r0 + i) * OP + c0 + j];
            }
    } else {
#pragma unroll
        for (int j = 0; j < 4; j++) {
            float bv = bias ? bias[c0 + j] : 0.f;
            acc[0][0][j] = bv; acc[0][1][j] = bv;
            acc[1][0][j] = bv; acc[1][1][j] = bv;
        }
    }
    const float* i00 = in0 + r0 * IN;
    const float* i01 = i00 + IN;
    const float* i10 = in1 + r0 * IN;
    const float* i11 = i10 + IN;
#pragma unroll 4
    for (int k = 0; k < IN; k += 4) {
        float4 w0 = *(const float4*)(W + (k + 0) * 64 + c0);
        float4 w1 = *(const float4*)(W + (k + 1) * 64 + c0);
        float4 w2 = *(const float4*)(W + (k + 2) * 64 + c0);
        float4 w3 = *(const float4*)(W + (k + 3) * 64 + c0);
        float4 a;
        a = *(const float4*)(i00 + k);
        fma4(acc[0][0], a.x, w0); fma4(acc[0][0], a.y, w1); fma4(acc[0][0], a.z, w2); fma4(acc[0][0], a.w, w3);
        a = *(const float4*)(i01 + k);
        fma4(acc[0][1], a.x, w0); fma4(acc[0][1], a.y, w1); fma4(acc[0][1], a.z, w2); fma4(acc[0][1], a.w, w3);
        a = *(const float4*)(i10 + k);
        fma4(acc[1][0], a.x, w0); fma4(acc[1][0], a.y, w1); fma4(acc[1][0], a.z, w2); fma4(acc[1][0], a.w, w3);
        a = *(const float4*)(i11 + k);
        fma4(acc[1][1], a.x, w0); fma4(acc[1][1], a.y, w1); fma4(acc[1][1], a.z, w2); fma4(acc[1][1], a.w, w3);
    }
#pragma unroll
    for (int i = 0; i < 2; i++)
#pragma unroll
        for (int j = 0; j < 4; j++) {
            float v0 = acc[0][i][j], v1 = acc[1][i][j];
            if (RELU) { v0 = fmaxf(v0, 0.f); v1 = fmaxf(v1, 0.f); }
            out0[(r0 + i) * OP + c0 + j] = v0;
            out1[(r0 + i) * OP + c0 + j] = v1;
        }
}

// agg GEMM (scalar, as in R11): aggX[32][64] = GX @ W3 + (31-2n)*b3
__device__ __forceinline__ void aggGemm_2(const float* __restrict__ G0,
                                          const float* __restrict__ G1,
                                          const float* __restrict__ W3,
                                          const float* __restrict__ b3,
                                          float* __restrict__ agg0,
                                          float* __restrict__ agg1, int tid)
{
    const int c0 = (tid & 15) * 4;
    const int r0 = (tid >> 4) * 2;
    const float sc0 = (float)(31 - 2 * r0);
    const float sc1 = (float)(31 - 2 * (r0 + 1));
    float acc[2][2][4];
#pragma unroll
    for (int j = 0; j < 4; j++) {
        float bv = b3[c0 + j];
        acc[0][0][j] = sc0 * bv; acc[0][1][j] = sc1 * bv;
        acc[1][0][j] = sc0 * bv; acc[1][1][j] = sc1 * bv;
    }
#pragma unroll 4
    for (int k = 0; k < 64; k += 4) {
        float4 w0 = *(const float4*)(W3 + (k + 0) * 64 + c0);
        float4 w1 = *(const float4*)(W3 + (k + 1) * 64 + c0);
        float4 w2 = *(const float4*)(W3 + (k + 2) * 64 + c0);
        float4 w3 = *(const float4*)(W3 + (k + 3) * 64 + c0);
        float4 a;
        a = *(const float4*)(G0 + r0 * 64 + k);
        fma4(acc[0][0], a.x, w0); fma4(acc[0][0], a.y, w1); fma4(acc[0][0], a.z, w2); fma4(acc[0][0], a.w, w3);
        a = *(const float4*)(G0 + (r0 + 1) * 64 + k);
        fma4(acc[0][1], a.x, w0); fma4(acc[0][1], a.y, w1); fma4(acc[0][1], a.z, w2); fma4(acc[0][1], a.w, w3);
        a = *(const float4*)(G1 + r0 * 64 + k);
        fma4(acc[1][0], a.x, w0); fma4(acc[1][0], a.y, w1); fma4(acc[1][0], a.z, w2); fma4(acc[1][0], a.w, w3);
        a = *(const float4*)(G1 + (r0 + 1) * 64 + k);
        fma4(acc[1][1], a.x, w0); fma4(acc[1][1], a.y, w1); fma4(acc[1][1], a.z, w2); fma4(acc[1][1], a.w, w3);
    }
#pragma unroll
    for (int i = 0; i < 2; i++)
#pragma unroll
        for (int j = 0; j < 4; j++) {
            agg0[(r0 + i) * 64 + c0 + j] = acc[0][i][j];
            agg1[(r0 + i) * 64 + c0 + j] = acc[1][i][j];
        }
}

__device__ __forceinline__ void layer_small_2(const float* __restrict__ in0,
                                              const float* __restrict__ in1, int IN,
                                              const float* __restrict__ W,
                                              const float* __restrict__ bias,
                                              float* __restrict__ out0,
                                              float* __restrict__ out1, int OUT,
                                              bool relu, int tid)
{
    for (int idx = tid; idx < 32 * OUT; idx += NT) {
        int r = idx / OUT, c = idx % OUT;
        float a0 = bias[c], a1 = a0;
        const float* i0 = in0 + r * IN;
        const float* i1 = in1 + r * IN;
#pragma unroll 4
        for (int k = 0; k < IN; k++) {
            float w = W[k * OUT + c];
            a0 = fmaf(i0[k], w, a0);
            a1 = fmaf(i1[k], w, a1);
        }
        out0[idx] = relu ? fmaxf(a0, 0.f) : a0;
        out1[idx] = relu ? fmaxf(a1, 0.f) : a1;
    }
}

__device__ __forceinline__ void acc_chunk2(const float* __restrict__ s0,
                                           const float* __restrict__ s1,
                                           const float* __restrict__ Wg,
                                           float acc[2][2][4], int r0, int c0)
{
    const float* a00 = s0 + r0 * 64;
    const float* a01 = a00 + 64;
    const float* a10 = s1 + r0 * 64;
    const float* a11 = a10 + 64;
#pragma unroll 4
    for (int k = 0; k < 64; k += 4) {
        float4 w0 = *(const float4*)(Wg + (k + 0) * 64 + c0);
        float4 w1 = *(const float4*)(Wg + (k + 1) * 64 + c0);
        float4 w2 = *(const float4*)(Wg + (k + 2) * 64 + c0);
        float4 w3 = *(const float4*)(Wg + (k + 3) * 64 + c0);
        float4 a;
        a = *(const float4*)(a00 + k);
        fma4(acc[0][0], a.x, w0); fma4(acc[0][0], a.y, w1); fma4(acc[0][0], a.z, w2); fma4(acc[0][0], a.w, w3);
        a = *(const float4*)(a01 + k);
        fma4(acc[0][1], a.x, w0); fma4(acc[0][1], a.y, w1); fma4(acc[0][1], a.z, w2); fma4(acc[0][1], a.w, w3);
        a = *(const float4*)(a10 + k);
        fma4(acc[1][0], a.x, w0); fma4(acc[1][0], a.y, w1); fma4(acc[1][0], a.z, w2); fma4(acc[1][0], a.w, w3);
        a = *(const float4*)(a11 + k);
        fma4(acc[1][1], a.x, w0); fma4(acc[1][1], a.y, w1); fma4(acc[1][1], a.z, w2); fma4(acc[1][1], a.w, w3);
    }
}

// per-warp HMMA edge GEMM for one batch: h2[512][H2P] = relu(relu(ya[ii]+yb[jj]) @ W2 + b2)
// B hi/lo from global pre-split arrays (pitch 64, L1-resident).
__device__ __forceinline__ void edge_gemm_mma(const float* __restrict__ ya,
                                              const float* __restrict__ yb,
                                              const unsigned short* __restrict__ Bth,
                                              const unsigned short* __restrict__ Btl,
                                              const float* __restrict__ b2s,
                                              float* __restrict__ h2f,
                                              const unsigned char* __restrict__ ii,
                                              const unsigned char* __restrict__ jj,
                                              int tid)
{
    const int wid = tid >> 5, lane = tid & 31;
    const int g = lane >> 2, t = lane & 3;
#pragma unroll 1
    for (int mt = 0; mt < 4; mt++) {
        const int tb = (wid * 4 + mt) * 16;
        const int r0 = tb + g, r1 = r0 + 8;
        const float* pa0 = ya + ii[r0] * YAP;
        const float* pb0 = yb + jj[r0] * YAP;
        const float* pa1 = ya + ii[r1] * YAP;
        const float* pb1 = yb + jj[r1] * YAP;
        unsigned Ahi[4][4], Alo[4][4];
#pragma unroll
        for (int ks = 0; ks < 4; ks++) {
            int c = ks * 16 + 2 * t;
            build_pair(pa0, pb0, c,     Ahi[ks][0], Alo[ks][0]);
            build_pair(pa1, pb1, c,     Ahi[ks][1], Alo[ks][1]);
            build_pair(pa0, pb0, c + 8, Ahi[ks][2], Alo[ks][2]);
            build_pair(pa1, pb1, c + 8, Ahi[ks][3], Alo[ks][3]);
        }
#pragma unroll
        for (int ns = 0; ns < 8; ns++) {
            const int n = ns * 8 + g;
            const unsigned short* bh = Bth + n * 64;
            const unsigned short* bl = Btl + n * 64;
            float da[4] = {0,0,0,0}, db[4] = {0,0,0,0}, dc[4] = {0,0,0,0};
#pragma unroll
            for (int ks = 0; ks < 4; ks++) {
                int kb = ks * 16 + 2 * t;
                unsigned bh0 = *(const unsigned*)(bh + kb);
                unsigned bh1 = *(const unsigned*)(bh + kb + 8);
                unsigned bl0 = *(const unsigned*)(bl + kb);
                unsigned bl1 = *(const unsigned*)(bl + kb + 8);
                mma16816(da, Ahi[ks], bh0, bh1);
                mma16816(db, Ahi[ks], bl0, bl1);
                mma16816(dc, Alo[ks], bh0, bh1);
            }
            int col = ns * 8 + 2 * t;
            float b0v = b2s[col], b1v = b2s[col + 1];
            float2 o0, o1;
            o0.x = fmaxf(da[0] + db[0] + dc[0] + b0v, 0.f);
            o0.y = fmaxf(da[1] + db[1] + dc[1] + b1v, 0.f);
            o1.x = fmaxf(da[2] + db[2] + dc[2] + b0v, 0.f);
            o1.y = fmaxf(da[3] + db[3] + dc[3] + b1v, 0.f);
            *(float2*)(h2f + r0 * H2P + col) = o0;
            *(float2*)(h2f + r1 * H2P + col) = o1;
        }
    }
}

// full edge block: 2 batches -> agg0/agg1 (scalar agg, as in R11)
__device__ void edge_full(const float* ya0, const float* ya1,
                          const float* yb0, const float* yb1,
                          const unsigned short* B2h, const unsigned short* B2l,
                          const float* b2s,
                          const float* __restrict__ W3g, const float* __restrict__ b3g,
                          float* h2f, float* Gs0, float* Gs1,
                          float* agg0, float* agg1,
                          const unsigned char* ii, const unsigned char* jj,
                          const unsigned short* jl, int tid)
{
    const int n = tid >> 3, c0s = (tid & 7) * 8;
    const int rs = n * 31 - ((n * (n - 1)) >> 1);
    const int iiend = rs + 31 - n;
    float g2[2][8];
#pragma unroll
    for (int j = 0; j < 8; j++) { g2[0][j] = 0.f; g2[1][j] = 0.f; }

#pragma unroll 1
    for (int b = 0; b < 2; b++) {
        edge_gemm_mma(b ? ya1 : ya0, b ? yb1 : yb0, B2h, B2l, b2s, h2f, ii, jj, tid);
        __syncthreads();
        float* g = g2[b];
        for (int p = rs; p < iiend; p++) {
            const float* r = h2f + p * H2P + c0s;
            float4 v0 = *(const float4*)r, v1 = *(const float4*)(r + 4);
            g[0] += v0.x; g[1] += v0.y; g[2] += v0.z; g[3] += v0.w;
            g[4] += v1.x; g[5] += v1.y; g[6] += v1.z; g[7] += v1.w;
        }
        for (int k = 0; k < n; k++) {
            int p = jl[(n << 5) + k];
            const float* r = h2f + p * H2P + c0s;
            float4 v0 = *(const float4*)r, v1 = *(const float4*)(r + 4);
            g[0] -= v0.x; g[1] -= v0.y; g[2] -= v0.z; g[3] -= v0.w;
            g[4] -= v1.x; g[5] -= v1.y; g[6] -= v1.z; g[7] -= v1.w;
        }
        __syncthreads();
    }
#pragma unroll
    for (int j = 0; j < 8; j++) {
        Gs0[n * 64 + c0s + j] = g2[0][j];
        Gs1[n * 64 + c0s + j] = g2[1][j];
    }
    __syncthreads();
    aggGemm_2(Gs0, Gs1, W3g, b3g, agg0, agg1, tid);
    __syncthreads();
}

__global__ void __launch_bounds__(NT, 1)
RelationalLatentDynamics_82849919140105_kernel(Params P)
{
    extern __shared__ char smb[];
    float* h2f = (float*)(smb + SM_H2);
    float* sc0  = h2f;            // scratch aliases in h2f
    float* sc1  = h2f + 4096;
    float* t0   = h2f + 8192;
    float* t1   = h2f + 10240;
    float* Gs0  = h2f + 12288;
    float* Gs1  = h2f + 14336;
    float* agg0 = h2f + 16384;
    float* agg1 = h2f + 18432;
    float* act = (float*)(smb + SM_ACT);
    float* ya0 = act;              float* ya1 = act + 2112;
    float* yb0 = act + 4224;       float* yb1 = act + 6336;
    float* zc0 = act + 8448;       float* zc1 = act + 10496;
    unsigned short* s_jl = (unsigned short*)(smb + SM_JL);
    unsigned char*  s_ii = (unsigned char*)(smb + SM_II);
    unsigned char*  s_jj = (unsigned char*)(smb + SM_JJ);
    float* b2s = (float*)(smb + SM_B2);

    const int tid = threadIdx.x;
    const int c0 = (tid & 15) * 4;
    const int r0 = (tid >> 4) * 2;

    // tables
    for (int p = tid; p < 512; p += NT) {
        if (p < 496) {
            int pp = p, i = 0;
            while (pp >= 31 - i) { pp -= 31 - i; i++; }
            s_ii[p] = (unsigned char)i;
            s_jj[p] = (unsigned char)(i + 1 + pp);
        } else { s_ii[p] = 0; s_jj[p] = 1; }
    }
    for (int idx = tid; idx < 1024; idx += NT) {
        int nn = idx >> 5, k = idx & 31;
        s_jl[idx] = (k < nn)
            ? (unsigned short)(k * 31 - ((k * (k - 1)) >> 1) + (nn - k - 1))
            : (unsigned short)0xFFFF;
    }
    if (tid < 64) b2s[tid] = P.ee2_b[tid];
    __syncthreads();

    const float* zb0 = P.z + (size_t)(2 * blockIdx.x) * (16 * 32 * 32);
    const float* zb1 = zb0 + 16 * 32 * 32;

    // ---- Phase A: ya/yb = src @ ee1_w (streamed; ee1_b folded into ya; pitch YAP) ----
    {
        float accA[2][2][4], accB[2][2][4];
#pragma unroll
        for (int j = 0; j < 4; j++) {
            float bv = P.ee1_b[c0 + j];
            accA[0][0][j] = bv; accA[0][1][j] = bv; accA[1][0][j] = bv; accA[1][1][j] = bv;
            accB[0][0][j] = 0.f; accB[0][1][j] = 0.f; accB[1][0][j] = 0.f; accB[1][1][j] = 0.f;
        }
#pragma unroll 1
        for (int ch = 0; ch < 8; ch++) {
            for (int idx = tid; idx < 2048; idx += NT) {
                int o = idx >> 6, fl = idx & 63;
                int t = 2 * ch + (fl >> 5), e = fl & 31;
                int off = (t * 32 + o) * 32 + e;
                float v0 = zb0[off], v1 = zb1[off];
                if (t > 0) { v0 -= zb0[off - 1024]; v1 -= zb1[off - 1024]; }
                sc0[o * 64 + fl] = v0;
                sc1[o * 64 + fl] = v1;
            }
            __syncthreads();
            acc_chunk2(sc0, sc1, P.ee1_w + ch * 4096, accA, r0, c0);
            acc_chunk2(sc0, sc1, P.ee1_w + 512 * 64 + ch * 4096, accB, r0, c0);
            __syncthreads();
        }
#pragma unroll
        for (int i = 0; i < 2; i++)
#pragma unroll
            for (int j = 0; j < 4; j++) {
                ya0[(r0 + i) * YAP + c0 + j] = accA[0][i][j];
                ya1[(r0 + i) * YAP + c0 + j] = accA[1][i][j];
                yb0[(r0 + i) * YAP + c0 + j] = accB[0][i][j];
                yb1[(r0 + i) * YAP + c0 + j] = accB[1][i][j];
            }
    }
    __syncthreads();

    // ---- ee edge block (HMMA; B from g_Bh[0]/g_Bl[0]) ----
    edge_full(ya0, ya1, yb0, yb1, g_Bh[0], g_Bl[0], b2s, P.ee3_w, P.ee3_b,
              h2f, Gs0, Gs1, agg0, agg1, s_ii, s_jj, s_jl, tid);

    // ---- ne MLP (scalar; ya reused pitch-64) ----
    layer2<64, false, false, 64>(agg0, agg1, P.ne1_w + 512 * 64, P.ne1_b, ya0, ya1, tid);
    {
        float acc[2][2][4];
#pragma unroll
        for (int i = 0; i < 2; i++)
#pragma unroll
            for (int j = 0; j < 4; j++) {
                acc[0][i][j] = ya0[(r0 + i) * 64 + c0 + j];   // own cells
                acc[1][i][j] = ya1[(r0 + i) * 64 + c0 + j];
            }
#pragma unroll 1
        for (int ch = 0; ch < 8; ch++) {
            for (int idx = tid; idx < 2048; idx += NT) {
                int o = idx >> 6, fl = idx & 63;
                int t = 2 * ch + (fl >> 5), e = fl & 31;
                int off = (t * 32 + o) * 32 + e;
                float v0 = zb0[off], v1 = zb1[off];
                if (t > 0) { v0 -= zb0[off - 1024]; v1 -= zb1[off - 1024]; }
                sc0[o * 64 + fl] = v0;
                sc1[o * 64 + fl] = v1;
            }
            __syncthreads();
            acc_chunk2(sc0, sc1, P.ne1_w + ch * 4096, acc, r0, c0);
            __syncthreads();
        }
#pragma unroll
        for (int i = 0; i < 2; i++)
#pragma unroll
            for (int j = 0; j < 4; j++) {
                ya0[(r0 + i) * 64 + c0 + j] = fmaxf(acc[0][i][j], 0.f);
                ya1[(r0 + i) * 64 + c0 + j] = fmaxf(acc[1][i][j], 0.f);
            }
    }
    __syncthreads();
    layer2<64, false, true, 64>(ya0, ya1, P.ne2_w, P.ne2_b, sc0, sc1, tid);
    __syncthreads();
    layer_small_2(sc0, sc1, 64, P.ne3_w, P.ne3_b, t0, t1, 32, true, tid);
    __syncthreads();
    layer_small_2(t0, t1, 32, P.ne4_w, P.ne4_b, sc0, sc1, 32, false, tid);  // z_impl
    __syncthreads();

    // zc = concat(z[b,-1], z_impl); restage le2 bias
    const float* zl0 = zb0 + 15 * 32 * 32;
    const float* zl1 = zb1 + 15 * 32 * 32;
    for (int idx = tid; idx < 2048; idx += NT) {
        int o = idx >> 6, c = idx & 63;
        zc0[idx] = (c < 32) ? zl0[o * 32 + c] : sc0[o * 32 + (c - 32)];
        zc1[idx] = (c < 32) ? zl1[o * 32 + c] : sc1[o * 32 + (c - 32)];
    }
    if (tid < 64) b2s[tid] = P.le2_b[tid];
    __syncthreads();

    // ---- rollout ----
    const int ostride = P.t_future * 1024;
    float* out0 = P.out + (size_t)(2 * blockIdx.x) * ostride;
    float* out1 = out0 + ostride;
#pragma unroll 1
    for (int t = 0; t < P.t_future; t++) {
        layer2<64, false, false, YAP>(zc0, zc1, P.le1_w,           P.le1_b, ya0, ya1, tid);
        layer2<64, false, false, YAP>(zc0, zc1, P.le1_w + 64 * 64, nullptr, yb0, yb1, tid);
        __syncthreads();
        edge_full(ya0, ya1, yb0, yb1, g_Bh[1], g_Bl[1], b2s, P.le3_w, P.le3_b,
                  h2f, Gs0, Gs1, agg0, agg1, s_ii, s_jj, s_jl, tid);

        layer2<64, false, false, 64>(zc0, zc1, P.lt1_w,            P.lt1_b, sc0, sc1, tid);
        layer2<64, true,  true,  64>(agg0, agg1, P.lt1_w + 64 * 64, nullptr, sc0, sc1, tid);
        __syncthreads();
        layer2<64, false, true, 64>(sc0, sc1, P.lt2_w, P.lt2_b, t0, t1, tid);
        __syncthreads();
        layer_small_2(t0, t1, 64, P.lt3_w, P.lt3_b, sc0, sc1, 32, true, tid);
        __syncthreads();
        layer_small_2(sc0, sc1, 32, P.lt4_w, P.lt4_b, t0, t1, 16, true, tid);
        __syncthreads();
        layer2<16, false, false, 64>(t0, t1, P.lt5_w, P.lt5_b, sc0, sc1, tid);  // delta
        __syncthreads();

        for (int idx = tid; idx < 2048; idx += NT) {
            float zn0 = zc0[idx] + sc0[idx];
            float zn1 = zc1[idx] + sc1[idx];
            zc0[idx] = zn0; zc1[idx] = zn1;
            int o = idx >> 6, c = idx & 63;
            if (c < 32) {
                out0[t * 1024 + o * 32 + c] = zn0;
                out1[t * 1024 + o * 32 + c] = zn1;
            }
        }
        __syncthreads();
    }
}

extern "C" void kernel_launch(void* const* d_in, const int* in_sizes, int n_in,
                              void* d_out, int out_size)
{
    Params P;
    int i = 0;
    P.z     = (const float*)d_in[i++];
    P.ee1_w = (const float*)d_in[i++]; P.ee1_b = (const float*)d_in[i++];
    P.ee2_w = (const float*)d_in[i++]; P.ee2_b = (const float*)d_in[i++];
    P.ee3_w = (const float*)d_in[i++]; P.ee3_b = (const float*)d_in[i++];
    P.ne1_w = (const float*)d_in[i++]; P.ne1_b = (const float*)d_in[i++];
    P.ne2_w = (const float*)d_in[i++]; P.ne2_b = (const float*)d_in[i++];
    P.ne3_w = (const float*)d_in[i++]; P.ne3_b = (const float*)d_in[i++];
    P.ne4_w = (const float*)d_in[i++]; P.ne4_b = (const float*)d_in[i++];
    P.le1_w = (const float*)d_in[i++]; P.le1_b = (const float*)d_in[i++];
    P.le2_w = (const float*)d_in[i++]; P.le2_b = (const float*)d_in[i++];
    P.le3_w = (const float*)d_in[i++]; P.le3_b = (const float*)d_in[i++];
    P.lt1_w = (const float*)d_in[i++]; P.lt1_b = (const float*)d_in[i++];
    P.lt2_w = (const float*)d_in[i++]; P.lt2_b = (const float*)d_in[i++];
    P.lt3_w = (const float*)d_in[i++]; P.lt3_b = (const float*)d_in[i++];
    P.lt4_w = (const float*)d_in[i++]; P.lt4_b = (const float*)d_in[i++];
    P.lt5_w = (const float*)d_in[i++]; P.lt5_b = (const float*)d_in[i++];
    P.out = (float*)d_out;
    P.t_future = out_size / (256 * 32 * 32);

    prep_kernel<<<2, 256>>>(P.ee2_w, P.le2_w);

    cudaFuncSetAttribute(RelationalLatentDynamics_82849919140105_kernel,
                         cudaFuncAttributeMaxDynamicSharedMemorySize, SMEM_BYTES);
    RelationalLatentDynamics_82849919140105_kernel<<<128, NT, SMEM_BYTES>>>(P);
}